// round 3
// baseline (speedup 1.0000x reference)
#include <cuda_runtime.h>
#include <cstdint>

#define D_DIM 768
#define K_CL  16
#define TPB   96          // threads per block (3 warps); TPB*8 = D_DIM
#define RR    4           // rows per block
#define PLANE (TPB*19 + 16)  // smem plane per row: 96 threads * 19-stride + 16-float row pad

typedef unsigned long long u64;

__device__ float g_c2[K_CL];

// ---- packed f32x2 helpers (sm_103a FFMA2 path; ptxas won't auto-fuse) ----
__device__ __forceinline__ u64 pack2(float lo, float hi) {
    u64 d; asm("mov.b64 %0, {%1, %2};" : "=l"(d) : "f"(lo), "f"(hi)); return d;
}
__device__ __forceinline__ float2 unpk(u64 v) {
    float2 r; asm("mov.b64 {%0, %1}, %2;" : "=f"(r.x), "=f"(r.y) : "l"(v)); return r;
}
__device__ __forceinline__ u64 fma2(u64 a, u64 b, u64 c) {
    u64 d; asm("fma.rn.f32x2 %0, %1, %2, %3;" : "=l"(d) : "l"(a), "l"(b), "l"(c)); return d;
}
__device__ __forceinline__ u64 mul2(u64 a, u64 b) {
    u64 d; asm("mul.rn.f32x2 %0, %1, %2;" : "=l"(d) : "l"(a), "l"(b)); return d;
}
__device__ __forceinline__ u64 add2(u64 a, u64 b) {
    u64 d; asm("add.rn.f32x2 %0, %1, %2;" : "=l"(d) : "l"(a), "l"(b)); return d;
}

// Precompute ||c_k||^2 once per launch sequence. 16 warps, one per centroid.
__global__ void c2_kernel(const float* __restrict__ cen) {
    int k = threadIdx.x >> 5;
    int lane = threadIdx.x & 31;
    float s = 0.f;
    #pragma unroll
    for (int i = 0; i < D_DIM / 32; i++) {
        float v = cen[k * D_DIM + lane + i * 32];
        s = fmaf(v, v, s);
    }
    #pragma unroll
    for (int o = 16; o > 0; o >>= 1) s += __shfl_xor_sync(0xffffffffu, s, o);
    if (lane == 0) g_c2[k] = s;
}

__global__ __launch_bounds__(TPB) void sln_kernel(
    const float* __restrict__ x, const float* __restrict__ wts,
    const float* __restrict__ bia, const float* __restrict__ cen,
    float* __restrict__ out, float* __restrict__ bkt, int write_bkt)
{
    __shared__ float part[RR * PLANE];   // per-(row,thread) partials: 16 dots + sum + sumsq
    __shared__ float tot[RR][20];        // reduced totals per row
    __shared__ float c2s[K_CL];

    const int u = threadIdx.x;
    const long long base_row = (long long)blockIdx.x * RR;

    if (u < K_CL) c2s[u] = g_c2[u];

    // ---- load x: RR rows x 8 floats/thread, keep packed in registers ----
    u64 xp[RR][4];
    float sum_[RR], sq_[RR];
    #pragma unroll
    for (int r = 0; r < RR; r++) {
        const float4* xr = (const float4*)(x + (base_row + r) * D_DIM) + u * 2;
        float4 a = xr[0], c = xr[1];
        xp[r][0] = pack2(a.x, a.y);
        xp[r][1] = pack2(a.z, a.w);
        xp[r][2] = pack2(c.x, c.y);
        xp[r][3] = pack2(c.z, c.w);
        sum_[r] = ((a.x + a.y) + (a.z + a.w)) + ((c.x + c.y) + (c.z + c.w));
        sq_[r]  = ((a.x*a.x + a.y*a.y) + (a.z*a.z + a.w*a.w))
                + ((c.x*c.x + c.y*c.y) + (c.z*c.z + c.w*c.w));
    }

    // ---- 16 centroid dot partials; centroid chunk loaded once, reused for 4 rows ----
    #pragma unroll
    for (int k = 0; k < K_CL; k++) {
        const float4* cr = (const float4*)(cen + k * D_DIM) + u * 2;
        float4 ca = cr[0], cb = cr[1];
        u64 c0 = pack2(ca.x, ca.y), c1 = pack2(ca.z, ca.w);
        u64 c2p = pack2(cb.x, cb.y), c3 = pack2(cb.z, cb.w);
        #pragma unroll
        for (int r = 0; r < RR; r++) {
            u64 acc = mul2(xp[r][0], c0);
            acc = fma2(xp[r][1], c1, acc);
            acc = fma2(xp[r][2], c2p, acc);
            acc = fma2(xp[r][3], c3, acc);
            float2 t = unpk(acc);
            part[r * PLANE + u * 19 + k] = t.x + t.y;
        }
    }
    #pragma unroll
    for (int r = 0; r < RR; r++) {
        part[r * PLANE + u * 19 + 16] = sum_[r];
        part[r * PLANE + u * 19 + 17] = sq_[r];
    }
    __syncthreads();

    // ---- stage 2: 72 jobs (18 values x 4 rows), each sums 96 entries ----
    if (u < 18 * RR) {
        int val = u % 18;
        int r = u / 18;
        const float* p = part + r * PLANE + val;
        float s = 0.f;
        #pragma unroll 8
        for (int i = 0; i < TPB; i++) s += p[i * 19];
        tot[r][val] = s;
    }
    __syncthreads();

    // ---- per-row stats + argmin (redundant across threads; cheap broadcasts) ----
    float mean[RR], rstd[RR];
    int sel[RR];
    #pragma unroll
    for (int r = 0; r < RR; r++) {
        float s = tot[r][16], q = tot[r][17];
        float m = s * (1.0f / D_DIM);
        float var = q * (1.0f / D_DIM) - m * m;
        mean[r] = m;
        rstd[r] = rsqrtf(var + 1e-5f);
        float best = 3.4e38f; int bi = 0;
        #pragma unroll
        for (int k = 0; k < K_CL; k++) {
            float dist = q - 2.0f * tot[r][k] + c2s[k];   // same formula as reference
            if (dist < best) { best = dist; bi = k; }      // strict < = first-min tie-break
        }
        sel[r] = bi;
    }

    // ---- epilogue: gather w/b for selected bucket, packed affine, vectorized store ----
    #pragma unroll
    for (int r = 0; r < RR; r++) {
        const ulonglong2* wr = (const ulonglong2*)(wts + sel[r] * D_DIM) + u * 2;
        const ulonglong2* br = (const ulonglong2*)(bia + sel[r] * D_DIM) + u * 2;
        ulonglong2 w0 = wr[0], w1 = wr[1];
        ulonglong2 b0 = br[0], b1 = br[1];
        u64 nm = pack2(-mean[r], -mean[r]);
        u64 rs = pack2(rstd[r], rstd[r]);
        u64 o0 = fma2(mul2(add2(xp[r][0], nm), rs), w0.x, b0.x);
        u64 o1 = fma2(mul2(add2(xp[r][1], nm), rs), w0.y, b0.y);
        u64 o2 = fma2(mul2(add2(xp[r][2], nm), rs), w1.x, b1.x);
        u64 o3 = fma2(mul2(add2(xp[r][3], nm), rs), w1.y, b1.y);
        ulonglong2* orow = (ulonglong2*)(out + (base_row + r) * D_DIM) + u * 2;
        orow[0] = make_ulonglong2(o0, o1);
        orow[1] = make_ulonglong2(o2, o3);
    }
    if (write_bkt && u == 0) {
        #pragma unroll
        for (int r = 0; r < RR; r++) bkt[base_row + r] = (float)sel[r];
    }
}

extern "C" void kernel_launch(void* const* d_in, const int* in_sizes, int n_in,
                              void* d_out, int out_size) {
    const float* x = (const float*)d_in[0];   // [B,S,D] f32
    const float* w = (const float*)d_in[1];   // [K,D]
    const float* b = (const float*)d_in[2];   // [K,D]
    const float* c = (const float*)d_in[3];   // [K,D]
    float* out = (float*)d_out;

    int rows = in_sizes[0] / D_DIM;           // 32768
    int wb = (out_size >= rows * D_DIM + rows) ? 1 : 0;
    float* bkt = out + (size_t)rows * D_DIM;

    c2_kernel<<<1, 512>>>(c);
    sln_kernel<<<rows / RR, TPB>>>(x, w, b, c, out, bkt, wb);
}

// round 4
// speedup vs baseline: 1.0448x; 1.0448x over previous
#include <cuda_runtime.h>
#include <cstdint>

#define D_DIM   768
#define K_CL    16
#define TPB     64          // threads per block (2 warps); TPB*EPT = D_DIM
#define EPT     12          // elements per thread (3 float4)
#define RR      8           // rows per block
#define NVAL    18          // 16 dots + sum + sumsq
#define PSTRIDE 68          // floats; 272B row: 16B-aligned for LDS.128, 4-way-bank (= phase min)

typedef unsigned long long u64;

__device__ float g_c2[K_CL];

// ---- packed f32x2 helpers (sm_103a FFMA2 path; ptxas won't auto-fuse) ----
__device__ __forceinline__ u64 pack2(float lo, float hi) {
    u64 d; asm("mov.b64 %0, {%1, %2};" : "=l"(d) : "f"(lo), "f"(hi)); return d;
}
__device__ __forceinline__ float2 unpk(u64 v) {
    float2 r; asm("mov.b64 {%0, %1}, %2;" : "=f"(r.x), "=f"(r.y) : "l"(v)); return r;
}
__device__ __forceinline__ u64 fma2(u64 a, u64 b, u64 c) {
    u64 d; asm("fma.rn.f32x2 %0, %1, %2, %3;" : "=l"(d) : "l"(a), "l"(b), "l"(c)); return d;
}
__device__ __forceinline__ u64 mul2(u64 a, u64 b) {
    u64 d; asm("mul.rn.f32x2 %0, %1, %2;" : "=l"(d) : "l"(a), "l"(b)); return d;
}
__device__ __forceinline__ u64 add2(u64 a, u64 b) {
    u64 d; asm("add.rn.f32x2 %0, %1, %2;" : "=l"(d) : "l"(a), "l"(b)); return d;
}

// Precompute ||c_k||^2 once per launch sequence. 16 warps, one per centroid.
__global__ void c2_kernel(const float* __restrict__ cen) {
    int k = threadIdx.x >> 5;
    int lane = threadIdx.x & 31;
    float s = 0.f;
    #pragma unroll
    for (int i = 0; i < D_DIM / 32; i++) {
        float v = cen[k * D_DIM + lane + i * 32];
        s = fmaf(v, v, s);
    }
    #pragma unroll
    for (int o = 16; o > 0; o >>= 1) s += __shfl_xor_sync(0xffffffffu, s, o);
    if (lane == 0) g_c2[k] = s;
}

__global__ __launch_bounds__(TPB) void sln_kernel(
    const float* __restrict__ x, const float* __restrict__ wts,
    const float* __restrict__ bia, const float* __restrict__ cen,
    float* __restrict__ out, float* __restrict__ bkt, int write_bkt)
{
    // value-major partial plane: row j = (r*NVAL + val), 64 thread-partials + pad
    __shared__ float part[RR * NVAL * PSTRIDE];      // ~38.3 KB
    __shared__ float tot[RR][NVAL + 2];
    __shared__ float c2s[K_CL];

    const int u = threadIdx.x;
    const long long base_row = (long long)blockIdx.x * RR;

    if (u < K_CL) c2s[u] = g_c2[u];

    // ---- load x: RR rows x 12 floats/thread, keep packed in registers ----
    u64 xp[RR][6];
    #pragma unroll
    for (int r = 0; r < RR; r++) {
        const float4* xr = (const float4*)(x + (base_row + r) * D_DIM + u * EPT);
        float4 a = xr[0], b = xr[1], c = xr[2];
        xp[r][0] = pack2(a.x, a.y); xp[r][1] = pack2(a.z, a.w);
        xp[r][2] = pack2(b.x, b.y); xp[r][3] = pack2(b.z, b.w);
        xp[r][4] = pack2(c.x, c.y); xp[r][5] = pack2(c.z, c.w);
        float sm = ((a.x + a.y) + (a.z + a.w)) + ((b.x + b.y) + (b.z + b.w))
                 + ((c.x + c.y) + (c.z + c.w));
        float sq = ((a.x*a.x + a.y*a.y) + (a.z*a.z + a.w*a.w))
                 + ((b.x*b.x + b.y*b.y) + (b.z*b.z + b.w*b.w))
                 + ((c.x*c.x + c.y*c.y) + (c.z*c.z + c.w*c.w));
        part[(r * NVAL + 16) * PSTRIDE + u] = sm;
        part[(r * NVAL + 17) * PSTRIDE + u] = sq;
    }

    // ---- 16 centroid dot partials; centroid chunk loaded once, reused for 8 rows ----
    #pragma unroll
    for (int k = 0; k < K_CL; k++) {
        const float4* cr = (const float4*)(cen + k * D_DIM + u * EPT);
        float4 ca = cr[0], cb = cr[1], cc = cr[2];
        u64 c0 = pack2(ca.x, ca.y), c1 = pack2(ca.z, ca.w);
        u64 c2p = pack2(cb.x, cb.y), c3 = pack2(cb.z, cb.w);
        u64 c4 = pack2(cc.x, cc.y), c5 = pack2(cc.z, cc.w);
        #pragma unroll
        for (int r = 0; r < RR; r++) {
            u64 acc = mul2(xp[r][0], c0);
            acc = fma2(xp[r][1], c1, acc);
            acc = fma2(xp[r][2], c2p, acc);
            acc = fma2(xp[r][3], c3, acc);
            acc = fma2(xp[r][4], c4, acc);
            acc = fma2(xp[r][5], c5, acc);
            float2 t = unpk(acc);
            part[(r * NVAL + k) * PSTRIDE + u] = t.x + t.y;
        }
    }
    __syncthreads();

    // ---- stage 2: 144 jobs (18 values x 8 rows), each sums 64 floats via LDS.128 ----
    #pragma unroll
    for (int j = u; j < RR * NVAL; j += TPB) {
        const float4* p = (const float4*)(part + j * PSTRIDE);
        float4 a0 = p[0], a1 = p[1], a2 = p[2], a3 = p[3];
        float s0 = (a0.x + a0.y) + (a0.z + a0.w);
        float s1 = (a1.x + a1.y) + (a1.z + a1.w);
        float s2 = (a2.x + a2.y) + (a2.z + a2.w);
        float s3 = (a3.x + a3.y) + (a3.z + a3.w);
        float4 b0 = p[4], b1 = p[5], b2 = p[6], b3 = p[7];
        s0 += (b0.x + b0.y) + (b0.z + b0.w);
        s1 += (b1.x + b1.y) + (b1.z + b1.w);
        s2 += (b2.x + b2.y) + (b2.z + b2.w);
        s3 += (b3.x + b3.y) + (b3.z + b3.w);
        float4 d0 = p[8], d1 = p[9], d2 = p[10], d3 = p[11];
        s0 += (d0.x + d0.y) + (d0.z + d0.w);
        s1 += (d1.x + d1.y) + (d1.z + d1.w);
        s2 += (d2.x + d2.y) + (d2.z + d2.w);
        s3 += (d3.x + d3.y) + (d3.z + d3.w);
        float4 e0 = p[12], e1 = p[13], e2 = p[14], e3 = p[15];
        s0 += (e0.x + e0.y) + (e0.z + e0.w);
        s1 += (e1.x + e1.y) + (e1.z + e1.w);
        s2 += (e2.x + e2.y) + (e2.z + e2.w);
        s3 += (e3.x + e3.y) + (e3.z + e3.w);
        tot[j / NVAL][j % NVAL] = (s0 + s1) + (s2 + s3);
    }
    __syncthreads();

    // ---- epilogue: per row recompute stats+argmin from tot (broadcast LDS), then affine ----
    #pragma unroll
    for (int r = 0; r < RR; r++) {
        float s = tot[r][16], q = tot[r][17];
        float m = s * (1.0f / D_DIM);
        float var = q * (1.0f / D_DIM) - m * m;
        float rstd = rsqrtf(var + 1e-5f);
        float best = 3.4e38f; int sel = 0;
        #pragma unroll
        for (int k = 0; k < K_CL; k++) {
            float dist = q - 2.0f * tot[r][k] + c2s[k];   // same formula as reference
            if (dist < best) { best = dist; sel = k; }     // strict < = first-min tie-break
        }

        const float4* wr = (const float4*)(wts + sel * D_DIM + u * EPT);
        const float4* br = (const float4*)(bia + sel * D_DIM + u * EPT);
        float4 w0 = wr[0], w1 = wr[1], w2 = wr[2];
        float4 b0 = br[0], b1 = br[1], b2 = br[2];
        u64 nm = pack2(-m, -m);
        u64 rs = pack2(rstd, rstd);
        u64 o0 = fma2(mul2(add2(xp[r][0], nm), rs), pack2(w0.x, w0.y), pack2(b0.x, b0.y));
        u64 o1 = fma2(mul2(add2(xp[r][1], nm), rs), pack2(w0.z, w0.w), pack2(b0.z, b0.w));
        u64 o2 = fma2(mul2(add2(xp[r][2], nm), rs), pack2(w1.x, w1.y), pack2(b1.x, b1.y));
        u64 o3 = fma2(mul2(add2(xp[r][3], nm), rs), pack2(w1.z, w1.w), pack2(b1.z, b1.w));
        u64 o4 = fma2(mul2(add2(xp[r][4], nm), rs), pack2(w2.x, w2.y), pack2(b2.x, b2.y));
        u64 o5 = fma2(mul2(add2(xp[r][5], nm), rs), pack2(w2.z, w2.w), pack2(b2.z, b2.w));
        ulonglong2* orow = (ulonglong2*)(out + (base_row + r) * D_DIM + u * EPT);
        orow[0] = make_ulonglong2(o0, o1);
        orow[1] = make_ulonglong2(o2, o3);
        orow[2] = make_ulonglong2(o4, o5);

        if (write_bkt && u == 0) bkt[base_row + r] = (float)sel;
    }
}

extern "C" void kernel_launch(void* const* d_in, const int* in_sizes, int n_in,
                              void* d_out, int out_size) {
    const float* x = (const float*)d_in[0];   // [B,S,D] f32
    const float* w = (const float*)d_in[1];   // [K,D]
    const float* b = (const float*)d_in[2];   // [K,D]
    const float* c = (const float*)d_in[3];   // [K,D]
    float* out = (float*)d_out;

    int rows = in_sizes[0] / D_DIM;           // 32768
    int wb = (out_size >= rows * D_DIM + rows) ? 1 : 0;
    float* bkt = out + (size_t)rows * D_DIM;

    c2_kernel<<<1, 512>>>(c);
    sln_kernel<<<rows / RR, TPB>>>(x, w, b, c, out, bkt, wb);
}

// round 5
// speedup vs baseline: 1.1671x; 1.1170x over previous
#include <cuda_runtime.h>
#include <cstdint>

#define D_DIM   768
#define K_CL    16
#define TPB     128         // 4 warps; TPB*EPT = D_DIM
#define EPT     6           // elements per thread (3 float2)
#define RR      8           // rows per block
#define NVAL    18          // 16 dots + sum + sumsq
#define NCOL    32          // partial columns after 4-lane pre-reduction (128/4)
#define PS      36          // plane stride (floats): 144B, 16B-aligned, conflict-free

typedef unsigned long long u64;

__device__ float g_c2[K_CL];

// ---- packed f32x2 helpers (sm_103a FFMA2 path; ptxas won't auto-fuse) ----
__device__ __forceinline__ u64 pack2(float lo, float hi) {
    u64 d; asm("mov.b64 %0, {%1, %2};" : "=l"(d) : "f"(lo), "f"(hi)); return d;
}
__device__ __forceinline__ float2 unpk(u64 v) {
    float2 r; asm("mov.b64 {%0, %1}, %2;" : "=f"(r.x), "=f"(r.y) : "l"(v)); return r;
}
__device__ __forceinline__ u64 fma2(u64 a, u64 b, u64 c) {
    u64 d; asm("fma.rn.f32x2 %0, %1, %2, %3;" : "=l"(d) : "l"(a), "l"(b), "l"(c)); return d;
}
__device__ __forceinline__ u64 mul2(u64 a, u64 b) {
    u64 d; asm("mul.rn.f32x2 %0, %1, %2;" : "=l"(d) : "l"(a), "l"(b)); return d;
}
__device__ __forceinline__ u64 add2(u64 a, u64 b) {
    u64 d; asm("add.rn.f32x2 %0, %1, %2;" : "=l"(d) : "l"(a), "l"(b)); return d;
}

// Precompute ||c_k||^2 once per launch sequence. 16 warps, one per centroid.
__global__ void c2_kernel(const float* __restrict__ cen) {
    int k = threadIdx.x >> 5;
    int lane = threadIdx.x & 31;
    float s = 0.f;
    #pragma unroll
    for (int i = 0; i < D_DIM / 32; i++) {
        float v = cen[k * D_DIM + lane + i * 32];
        s = fmaf(v, v, s);
    }
    #pragma unroll
    for (int o = 16; o > 0; o >>= 1) s += __shfl_xor_sync(0xffffffffu, s, o);
    if (lane == 0) g_c2[k] = s;
}

__global__ __launch_bounds__(TPB, 4) void sln_kernel(
    const float* __restrict__ x, const float* __restrict__ wts,
    const float* __restrict__ bia, const float* __restrict__ cen,
    float* __restrict__ out, float* __restrict__ bkt, int write_bkt)
{
    __shared__ float part[RR * NVAL * PS];   // 20.7 KB: 4-lane-pre-reduced partials
    __shared__ float tot[RR][NVAL + 2];
    __shared__ float c2s[K_CL];

    const int u = threadIdx.x;
    const int lane = u & 31;
    const int col = u >> 2;                  // 0..31 after 4-lane group reduction
    const long long base_row = (long long)blockIdx.x * RR;

    if (u < K_CL) c2s[u] = g_c2[u];

    // ---- load x: RR rows x 6 floats/thread as 3 packed f32x2 each ----
    u64 xp[RR][3];
    float sm[RR], sq[RR];
    #pragma unroll
    for (int r = 0; r < RR; r++) {
        const u64* xr = (const u64*)(x + (base_row + r) * D_DIM + u * EPT);
        xp[r][0] = xr[0]; xp[r][1] = xr[1]; xp[r][2] = xr[2];
        u64 s2 = add2(xp[r][0], add2(xp[r][1], xp[r][2]));
        u64 q2 = mul2(xp[r][0], xp[r][0]);
        q2 = fma2(xp[r][1], xp[r][1], q2);
        q2 = fma2(xp[r][2], xp[r][2], q2);
        float2 ts = unpk(s2), tq = unpk(q2);
        sm[r] = ts.x + ts.y;
        sq[r] = tq.x + tq.y;
    }
    // pre-reduce sum/sumsq across 4-lane groups (rows packed in pairs)
    #pragma unroll
    for (int ri = 0; ri < RR / 2; ri++) {
        u64 sp = pack2(sm[2 * ri], sm[2 * ri + 1]);
        u64 qp = pack2(sq[2 * ri], sq[2 * ri + 1]);
        sp = add2(sp, __shfl_down_sync(0xffffffffu, sp, 1));
        sp = add2(sp, __shfl_down_sync(0xffffffffu, sp, 2));
        qp = add2(qp, __shfl_down_sync(0xffffffffu, qp, 1));
        qp = add2(qp, __shfl_down_sync(0xffffffffu, qp, 2));
        if ((lane & 3) == 0) {
            float2 a = unpk(sp), b = unpk(qp);
            part[((2 * ri)     * NVAL + 16) * PS + col] = a.x;
            part[((2 * ri + 1) * NVAL + 16) * PS + col] = a.y;
            part[((2 * ri)     * NVAL + 17) * PS + col] = b.x;
            part[((2 * ri + 1) * NVAL + 17) * PS + col] = b.y;
        }
    }

    // ---- 16 centroid dot partials; centroid chunk loaded once, reused for 8 rows ----
    #pragma unroll
    for (int k = 0; k < K_CL; k++) {
        const u64* cr = (const u64*)(cen + k * D_DIM + u * EPT);
        u64 c0 = cr[0], c1 = cr[1], c2p = cr[2];
        float d[RR];
        #pragma unroll
        for (int r = 0; r < RR; r++) {
            u64 acc = mul2(xp[r][0], c0);
            acc = fma2(xp[r][1], c1, acc);
            acc = fma2(xp[r][2], c2p, acc);
            float2 t = unpk(acc);
            d[r] = t.x + t.y;
        }
        #pragma unroll
        for (int ri = 0; ri < RR / 2; ri++) {
            u64 dp = pack2(d[2 * ri], d[2 * ri + 1]);
            dp = add2(dp, __shfl_down_sync(0xffffffffu, dp, 1));
            dp = add2(dp, __shfl_down_sync(0xffffffffu, dp, 2));
            if ((lane & 3) == 0) {
                float2 t = unpk(dp);
                part[((2 * ri)     * NVAL + k) * PS + col] = t.x;
                part[((2 * ri + 1) * NVAL + k) * PS + col] = t.y;
            }
        }
    }
    __syncthreads();

    // ---- stage 2: 144 jobs (18 vals x 8 rows), each sums 32 floats via LDS.128 ----
    for (int j = u; j < RR * NVAL; j += TPB) {
        const float4* p = (const float4*)(part + j * PS);
        float4 a0 = p[0], a1 = p[1], a2 = p[2], a3 = p[3];
        float4 b0 = p[4], b1 = p[5], b2 = p[6], b3 = p[7];
        float s0 = ((a0.x + a0.y) + (a0.z + a0.w)) + ((b0.x + b0.y) + (b0.z + b0.w));
        float s1 = ((a1.x + a1.y) + (a1.z + a1.w)) + ((b1.x + b1.y) + (b1.z + b1.w));
        float s2 = ((a2.x + a2.y) + (a2.z + a2.w)) + ((b2.x + b2.y) + (b2.z + b2.w));
        float s3 = ((a3.x + a3.y) + (a3.z + a3.w)) + ((b3.x + b3.y) + (b3.z + b3.w));
        tot[j / NVAL][j % NVAL] = (s0 + s1) + (s2 + s3);
    }
    __syncthreads();

    // ---- epilogue: per-row stats + argmin from tot (broadcast LDS), packed affine ----
    #pragma unroll
    for (int r = 0; r < RR; r++) {
        float s = tot[r][16], q = tot[r][17];
        float m = s * (1.0f / D_DIM);
        float var = q * (1.0f / D_DIM) - m * m;
        float rstd = rsqrtf(var + 1e-5f);
        float best = 3.4e38f; int sel = 0;
        #pragma unroll
        for (int k = 0; k < K_CL; k++) {
            float dist = q - 2.0f * tot[r][k] + c2s[k];   // same formula as reference
            if (dist < best) { best = dist; sel = k; }     // strict < = first-min tie-break
        }

        const u64* wr = (const u64*)(wts + sel * D_DIM + u * EPT);
        const u64* br = (const u64*)(bia + sel * D_DIM + u * EPT);
        u64 w0 = wr[0], w1 = wr[1], w2 = wr[2];
        u64 b0 = br[0], b1 = br[1], b2 = br[2];
        u64 nm = pack2(-m, -m);
        u64 rs = pack2(rstd, rstd);
        u64 o0 = fma2(mul2(add2(xp[r][0], nm), rs), w0, b0);
        u64 o1 = fma2(mul2(add2(xp[r][1], nm), rs), w1, b1);
        u64 o2 = fma2(mul2(add2(xp[r][2], nm), rs), w2, b2);
        u64* orow = (u64*)(out + (base_row + r) * D_DIM + u * EPT);
        orow[0] = o0; orow[1] = o1; orow[2] = o2;

        if (write_bkt && u == 0) bkt[base_row + r] = (float)sel;
    }
}

extern "C" void kernel_launch(void* const* d_in, const int* in_sizes, int n_in,
                              void* d_out, int out_size) {
    const float* x = (const float*)d_in[0];   // [B,S,D] f32
    const float* w = (const float*)d_in[1];   // [K,D]
    const float* b = (const float*)d_in[2];   // [K,D]
    const float* c = (const float*)d_in[3];   // [K,D]
    float* out = (float*)d_out;

    int rows = in_sizes[0] / D_DIM;           // 32768
    int wb = (out_size >= rows * D_DIM + rows) ? 1 : 0;
    float* bkt = out + (size_t)rows * D_DIM;

    c2_kernel<<<1, 512>>>(c);
    sln_kernel<<<rows / RR, TPB>>>(x, w, b, c, out, bkt, wb);
}